// round 6
// baseline (speedup 1.0000x reference)
#include <cuda_runtime.h>
#include <math.h>

#define NROWS 500000
#define NA 5
#define TT 8
#define NE 18
#define MB 4
#define EPSV 1e-8f
#define ML2 (0.02f * 0.02f)
#define BLK 128
#define NCLS (NE * MB * TT)   // 576

__global__ void zero_out_kernel(float* out) { out[0] = 0.0f; }

__device__ __forceinline__ float sqrt_approx(float a) {
    float r; asm("sqrt.approx.f32 %0, %1;" : "=f"(r) : "f"(a)); return r;
}
__device__ __forceinline__ float rcp_approx(float a) {
    float r; asm("rcp.approx.f32 %0, %1;" : "=f"(r) : "f"(a)); return r;
}

__global__ void __launch_bounds__(BLK, 8) loss_kernel(
    const float* __restrict__ x,
    const float* __restrict__ yt,
    const float* __restrict__ yp,
    const float* __restrict__ mk,
    const int* __restrict__ trip,
    const int* __restrict__ tvalid,
    float* __restrict__ out)
{
    __shared__ unsigned s_pk[NCLS];          // packed (ii,jj,kk,ok): 2.3 KB, 16B-aligned rows of 8
    __shared__ float st[BLK * 15];
    __shared__ float sp[BLK * 15];
    __shared__ float sm[BLK * 15];
    __shared__ float warpsum[BLK / 32];

    const int tid = threadIdx.x;

    // Pack tables: indices in [-1,4] -> clamp to [0,4] (4 bits each), validity 1 bit.
    for (int e = tid; e < NCLS; e += BLK) {
        const int i0 = trip[3 * e + 0];
        const int i1 = trip[3 * e + 1];
        const int i2 = trip[3 * e + 2];
        const int v  = tvalid[e];
        const unsigned ok = (i0 >= 0 && i1 >= 0 && i2 >= 0 && v > 0) ? 1u : 0u;
        const unsigned ii = (unsigned)max(i0, 0);
        const unsigned jj = (unsigned)max(i1, 0);
        const unsigned kk = (unsigned)max(i2, 0);
        s_pk[e] = ii | (jj << 4) | (kk << 8) | (ok << 12);
    }

    const int row0 = blockIdx.x * BLK;
    const int cnt  = min(BLK, NROWS - row0);

    if (cnt == BLK) {
        // full block: 1920 floats = 480 float4 per array, 16B-aligned
        const float4* gt4 = (const float4*)(yt + (size_t)row0 * 15);
        const float4* gp4 = (const float4*)(yp + (size_t)row0 * 15);
        const float4* gm4 = (const float4*)(mk + (size_t)row0 * 15);
        float4* st4 = (float4*)st;
        float4* sp4 = (float4*)sp;
        float4* sm4 = (float4*)sm;
#pragma unroll
        for (int i = 0; i < 4; i++) {
            int idx = tid + i * BLK;
            if (idx < (BLK * 15) / 4) {
                st4[idx] = gt4[idx];
                sp4[idx] = gp4[idx];
                sm4[idx] = gm4[idx];
            }
        }
    } else {
        const int tot = cnt * 15;
        const float* gt = yt + (size_t)row0 * 15;
        const float* gp = yp + (size_t)row0 * 15;
        const float* gm = mk + (size_t)row0 * 15;
        for (int i = tid; i < tot; i += BLK) {
            st[i] = gt[i];
            sp[i] = gp[i];
            sm[i] = gm[i];
        }
    }
    __syncthreads();

    float acc = 0.0f;

    if (tid < cnt) {
        const float* t = st + tid * 15;   // stride 15: conflict-free (gcd(15,32)=1)
        const float* p = sp + tid * 15;
        const float* m = sm + tid * 15;

        // ---------------- atom MSE ----------------
        float num = 0.0f, den = 0.0f;
        unsigned avmask = 0;
#pragma unroll
        for (int a = 0; a < NA; a++) {
            float m0 = m[a * 3 + 0], m1 = m[a * 3 + 1], m2 = m[a * 3 + 2];
            float d0 = t[a * 3 + 0] - p[a * 3 + 0];
            float d1 = t[a * 3 + 1] - p[a * 3 + 1];
            float d2 = t[a * 3 + 2] - p[a * 3 + 2];
            float se = d0 * d0 * m0 + d1 * d1 * m1 + d2 * d2 * m2;
            bool v = (m0 > 0.0f) || (m1 > 0.0f) || (m2 > 0.0f);
            if (v) { num += se; den += 1.0f; avmask |= (1u << a); }
        }
        float atom = num * rcp_approx(den + EPSV);

        // ---------------- angle loss ----------------
        const int row = row0 + tid;
        // (row*38+36)*4 bytes: 8B-aligned -> single LDG.64
        const float2 xg = *(const float2*)(x + (size_t)row * 38 + 36);
        float bd = xg.x, gate = xg.y;
        if (!isfinite(gate)) gate = 0.0f;
        int rid = (int)rintf(gate) - 1;
        rid = min(max(rid, 0), NE - 1);
        if (!isfinite(bd)) bd = 0.0f;
        int bid = min(max((int)rintf(bd), 0), MB - 1);

        const int base = (rid * MB + bid) * TT;      // multiple of 8 -> 32B aligned
        const uint4* pkp = (const uint4*)(s_pk + base);

        const float lo = -1.0f + 1e-6f, hi = 1.0f - 1e-6f;
        float anum = 0.0f, aden = 0.0f;

#pragma unroll
        for (int h = 0; h < 2; h++) {
            const uint4 pk4 = pkp[h];
            const unsigned pkw[4] = { pk4.x, pk4.y, pk4.z, pk4.w };
#pragma unroll
            for (int e = 0; e < 4; e++) {
                const unsigned pk = pkw[e];
                const int ii = pk & 15;
                const int jj = (pk >> 4) & 15;
                const int kk = (pk >> 8) & 15;
                unsigned okb = (pk >> 12) & (avmask >> ii) & (avmask >> jj) & (avmask >> kk) & 1u;

                // ---- true side ----
                float tjx = t[jj * 3 + 0], tjy = t[jj * 3 + 1], tjz = t[jj * 3 + 2];
                float a1x = t[ii * 3 + 0] - tjx, a1y = t[ii * 3 + 1] - tjy, a1z = t[ii * 3 + 2] - tjz;
                float a2x = t[kk * 3 + 0] - tjx, a2y = t[kk * 3 + 1] - tjy, a2z = t[kk * 3 + 2] - tjz;
                float l1t = a1x * a1x + a1y * a1y + a1z * a1z;
                float l2t = a2x * a2x + a2y * a2y + a2z * a2z;
                float ddt = a1x * a2x + a1y * a2y + a1z * a2z;
                // cos = dot * rsqrt(l1*l2); sin = |u1 x u2| = sqrt(1 - cos^2) for unit vectors
                float ct = ddt * rsqrtf(fmaxf(l1t, ML2) * fmaxf(l2t, ML2));
                float sint = sqrt_approx(fmaxf(1.0f - ct * ct, 0.0f));
                ct = fminf(fmaxf(ct, lo), hi);

                // ---- pred side ----
                float pjx = p[jj * 3 + 0], pjy = p[jj * 3 + 1], pjz = p[jj * 3 + 2];
                float b1x = p[ii * 3 + 0] - pjx, b1y = p[ii * 3 + 1] - pjy, b1z = p[ii * 3 + 2] - pjz;
                float b2x = p[kk * 3 + 0] - pjx, b2y = p[kk * 3 + 1] - pjy, b2z = p[kk * 3 + 2] - pjz;
                float l1p = b1x * b1x + b1y * b1y + b1z * b1z;
                float l2p = b2x * b2x + b2y * b2y + b2z * b2z;
                float ddp = b1x * b2x + b1y * b2y + b1z * b2z;
                float cp = ddp * rsqrtf(fmaxf(l1p, ML2) * fmaxf(l2p, ML2));
                float sinp = sqrt_approx(fmaxf(1.0f - cp * cp, 0.0f));
                cp = fminf(fmaxf(cp, lo), hi);

                bool ok = okb && (l1t > ML2) && (l2t > ML2) && (l1p > ML2) && (l2p > ML2);

                float dc = cp - ct;
                float ds = sinp - sint;
                if (ok) { anum += dc * dc + ds * ds; aden += 1.0f; }
            }
        }
        float ang = anum * rcp_approx(aden + EPSV);

        acc = atom + ang;
    }

    // ---------------- block reduction ----------------
#pragma unroll
    for (int off = 16; off > 0; off >>= 1)
        acc += __shfl_down_sync(0xffffffffu, acc, off);

    if ((tid & 31) == 0) warpsum[tid >> 5] = acc;
    __syncthreads();
    if (tid == 0) {
        float s = 0.0f;
#pragma unroll
        for (int w = 0; w < BLK / 32; w++) s += warpsum[w];
        atomicAdd(out, s * (1.0f / (float)NROWS));
    }
}

extern "C" void kernel_launch(void* const* d_in, const int* in_sizes, int n_in,
                              void* d_out, int out_size)
{
    const float* x      = (const float*)d_in[0];
    const float* yt     = (const float*)d_in[1];
    const float* yp     = (const float*)d_in[2];
    const float* mk     = (const float*)d_in[3];
    const int*   trip   = (const int*)d_in[4];
    const int*   tvalid = (const int*)d_in[5];
    float* out = (float*)d_out;

    zero_out_kernel<<<1, 1>>>(out);
    const int grid = (NROWS + BLK - 1) / BLK;
    loss_kernel<<<grid, BLK>>>(x, yt, yp, mk, trip, tvalid, out);
}

// round 7
// speedup vs baseline: 1.0577x; 1.0577x over previous
#include <cuda_runtime.h>
#include <math.h>

#define NROWS 500000
#define NA 5
#define TT 8
#define NE 18
#define MB 4
#define EPSV 1e-8f
#define ML2 (0.02f * 0.02f)
#define BLK 128
#define NCLS (NE * MB * TT)   // 576

__global__ void zero_out_kernel(float* out) { out[0] = 0.0f; }

__device__ __forceinline__ float sqrt_approx(float a) {
    float r; asm("sqrt.approx.f32 %0, %1;" : "=f"(r) : "f"(a)); return r;
}
__device__ __forceinline__ float rcp_approx(float a) {
    float r; asm("rcp.approx.f32 %0, %1;" : "=f"(r) : "f"(a)); return r;
}

__global__ void __launch_bounds__(BLK, 10) loss_kernel(
    const float* __restrict__ x,
    const float* __restrict__ yt,
    const float* __restrict__ yp,
    const float* __restrict__ mk,
    const int* __restrict__ trip,
    const int* __restrict__ tvalid,
    float* __restrict__ out)
{
    __shared__ __align__(16) unsigned s_pk[NCLS];   // packed (ii,jj,kk,ok): 2.3 KB
    __shared__ __align__(16) float2  s_tp[BLK * 15]; // interleaved {true, pred}: 15 KB
    __shared__ float warpsum[BLK / 32];

    const int tid  = threadIdx.x;
    const int row0 = blockIdx.x * BLK;
    const int cnt  = min(BLK, NROWS - row0);
    const bool live = (tid < cnt);
    const int row  = row0 + tid;

    // -------- early per-thread mask load (binary 0/1 values -> 15-bit mask) --------
    unsigned mb = 0;
    if (live) {
        const float* mrow = mk + (size_t)row * 15;
#pragma unroll
        for (int e = 0; e < 15; e++)
            mb |= (mrow[e] > 0.0f ? 1u : 0u) << e;
    }
    // early gate/bead load too (overlaps staging)
    float gate = 0.0f, bd = 0.0f;
    if (live) {
        const float2 xg = *(const float2*)(x + (size_t)row * 38 + 36);
        bd = xg.x; gate = xg.y;
    }

    // -------- pack tables --------
    for (int e = tid; e < NCLS; e += BLK) {
        const int i0 = trip[3 * e + 0];
        const int i1 = trip[3 * e + 1];
        const int i2 = trip[3 * e + 2];
        const int v  = tvalid[e];
        const unsigned ok = (i0 >= 0 && i1 >= 0 && i2 >= 0 && v > 0) ? 1u : 0u;
        const unsigned ii = (unsigned)max(i0, 0);
        const unsigned jj = (unsigned)max(i1, 0);
        const unsigned kk = (unsigned)max(i2, 0);
        s_pk[e] = ii | (jj << 4) | (kk << 8) | (ok << 12);
    }

    // -------- stage y_true/y_pred interleaved --------
    if (cnt == BLK) {
        // 1920 floats per array = 960 float2; build {t,p} pairs in regs, store STS.128
        const float2* gt2 = (const float2*)(yt + (size_t)row0 * 15);
        const float2* gp2 = (const float2*)(yp + (size_t)row0 * 15);
        float4* d4 = (float4*)s_tp;
#pragma unroll
        for (int k = 0; k < 8; k++) {
            int i = tid + k * BLK;
            if (i < 960) {
                float2 a = gt2[i];
                float2 b = gp2[i];
                d4[i] = make_float4(a.x, b.x, a.y, b.y);  // s_tp[2i], s_tp[2i+1]
            }
        }
    } else {
        const int tot = cnt * 15;
        const float* gt = yt + (size_t)row0 * 15;
        const float* gp = yp + (size_t)row0 * 15;
        for (int i = tid; i < tot; i += BLK)
            s_tp[i] = make_float2(gt[i], gp[i]);
    }
    __syncthreads();

    float acc = 0.0f;

    if (live) {
        const float2* tp = s_tp + tid * 15;  // lane stride 120B: conflict-free per 16-lane phase

        // ---------------- atom MSE ----------------
        float num = 0.0f, den = 0.0f;
        unsigned avmask = 0;
#pragma unroll
        for (int a = 0; a < NA; a++) {
            float2 q0 = tp[3 * a + 0];
            float2 q1 = tp[3 * a + 1];
            float2 q2 = tp[3 * a + 2];
            float d0 = q0.x - q0.y, d1 = q1.x - q1.y, d2 = q2.x - q2.y;
            unsigned g = (mb >> (3 * a)) & 7u;
            float se = ((g & 1u) ? d0 * d0 : 0.0f)
                     + ((g & 2u) ? d1 * d1 : 0.0f)
                     + ((g & 4u) ? d2 * d2 : 0.0f);
            if (g) { num += se; den += 1.0f; avmask |= (1u << a); }
        }
        float atom = num * rcp_approx(den + EPSV);

        // ---------------- angle loss ----------------
        if (!isfinite(gate)) gate = 0.0f;
        int rid = (int)rintf(gate) - 1;
        rid = min(max(rid, 0), NE - 1);
        if (!isfinite(bd)) bd = 0.0f;
        int bid = min(max((int)rintf(bd), 0), MB - 1);

        const int base = (rid * MB + bid) * TT;      // multiple of 8 -> 32B aligned
        const uint4* pkp = (const uint4*)(s_pk + base);

        const float lo = -1.0f + 1e-6f, hi = 1.0f - 1e-6f;
        float anum = 0.0f, aden = 0.0f;

#pragma unroll
        for (int h = 0; h < 2; h++) {
            const uint4 pk4 = pkp[h];
            const unsigned pkw[4] = { pk4.x, pk4.y, pk4.z, pk4.w };
#pragma unroll
            for (int e = 0; e < 4; e++) {
                const unsigned pk = pkw[e];
                const int ii = pk & 15;
                const int jj = (pk >> 4) & 15;
                const int kk = (pk >> 8) & 15;
                unsigned okb = (pk >> 12) & (avmask >> ii) & (avmask >> jj) & (avmask >> kk) & 1u;

                // one LDS.64 per component serves BOTH true (.x) and pred (.y)
                float2 j0 = tp[jj * 3 + 0], j1 = tp[jj * 3 + 1], j2 = tp[jj * 3 + 2];
                float2 i0 = tp[ii * 3 + 0], i1 = tp[ii * 3 + 1], i2 = tp[ii * 3 + 2];
                float2 k0 = tp[kk * 3 + 0], k1 = tp[kk * 3 + 1], k2 = tp[kk * 3 + 2];

                // ---- true side ----
                float a1x = i0.x - j0.x, a1y = i1.x - j1.x, a1z = i2.x - j2.x;
                float a2x = k0.x - j0.x, a2y = k1.x - j1.x, a2z = k2.x - j2.x;
                float l1t = a1x * a1x + a1y * a1y + a1z * a1z;
                float l2t = a2x * a2x + a2y * a2y + a2z * a2z;
                float ddt = a1x * a2x + a1y * a2y + a1z * a2z;
                float ct = ddt * rsqrtf(fmaxf(l1t, ML2) * fmaxf(l2t, ML2));
                float sint = sqrt_approx(fmaxf(1.0f - ct * ct, 0.0f));
                ct = fminf(fmaxf(ct, lo), hi);

                // ---- pred side ----
                float b1x = i0.y - j0.y, b1y = i1.y - j1.y, b1z = i2.y - j2.y;
                float b2x = k0.y - j0.y, b2y = k1.y - j1.y, b2z = k2.y - j2.y;
                float l1p = b1x * b1x + b1y * b1y + b1z * b1z;
                float l2p = b2x * b2x + b2y * b2y + b2z * b2z;
                float ddp = b1x * b2x + b1y * b2y + b1z * b2z;
                float cp = ddp * rsqrtf(fmaxf(l1p, ML2) * fmaxf(l2p, ML2));
                float sinp = sqrt_approx(fmaxf(1.0f - cp * cp, 0.0f));
                cp = fminf(fmaxf(cp, lo), hi);

                bool ok = okb && (l1t > ML2) && (l2t > ML2) && (l1p > ML2) && (l2p > ML2);

                float dc = cp - ct;
                float ds = sinp - sint;
                if (ok) { anum += dc * dc + ds * ds; aden += 1.0f; }
            }
        }
        float ang = anum * rcp_approx(aden + EPSV);

        acc = atom + ang;
    }

    // ---------------- block reduction ----------------
#pragma unroll
    for (int off = 16; off > 0; off >>= 1)
        acc += __shfl_down_sync(0xffffffffu, acc, off);

    if ((tid & 31) == 0) warpsum[tid >> 5] = acc;
    __syncthreads();
    if (tid == 0) {
        float s = 0.0f;
#pragma unroll
        for (int w = 0; w < BLK / 32; w++) s += warpsum[w];
        atomicAdd(out, s * (1.0f / (float)NROWS));
    }
}

extern "C" void kernel_launch(void* const* d_in, const int* in_sizes, int n_in,
                              void* d_out, int out_size)
{
    const float* x      = (const float*)d_in[0];
    const float* yt     = (const float*)d_in[1];
    const float* yp     = (const float*)d_in[2];
    const float* mk     = (const float*)d_in[3];
    const int*   trip   = (const int*)d_in[4];
    const int*   tvalid = (const int*)d_in[5];
    float* out = (float*)d_out;

    zero_out_kernel<<<1, 1>>>(out);
    const int grid = (NROWS + BLK - 1) / BLK;
    loss_kernel<<<grid, BLK>>>(x, yt, yp, mk, trip, tvalid, out);
}